// round 9
// baseline (speedup 1.0000x reference)
#include <cuda_runtime.h>
#include <math.h>
#include <stdint.h>
#include <stddef.h>

typedef unsigned long long ull;

// Problem dims
static constexpr int S_LEN = 512;
static constexpr int BATCH = 64;
static constexpr int IDIM  = 256;
static constexpr int HDIM  = 512;
static constexpr int EDIM  = 512;

// 128 worker CTAs = 32 clusters x 4 k-split ranks; warp-specialized h/a pipelines
static constexpr int GW  = 128;
static constexpr int NT  = 512;   // warps 0-7: h-pipe, warps 8-15: a-pipe

// smem byte offsets
static constexpr int OFF_WHD   = 0;        // 128k x 16c ull dup   = 16384
static constexpr int OFF_WAD   = 16384;    // 256k x 16c ull dup   = 32768
static constexpr int OFF_REDH  = 49152;    // 8w x 16c x 32bp ull  = 32768
static constexpr int OFF_REDA  = 81920;    // 8w x 16c x 32bp ull  = 32768
static constexpr int OFF_MBOXH = 114688;   // 4src x 4c x 32bp ull = 4096
static constexpr int OFF_MBOXA = 118784;   // 4096
static constexpr int OFF_MBFH  = 122880;   // 4 ints
static constexpr int OFF_MBFA  = 122896;   // 4 ints
static constexpr int SMEM_BYTES = 123008;

// Device scratch (allocation-free rule)
__device__ float g_xw[(size_t)S_LEN * HDIM * BATCH];          // [t][c][b]
__device__ float g_hall[(size_t)(S_LEN + 1) * HDIM * BATCH];  // [t][c][b], h_0..h_512
__device__ float g_a[2][EDIM * BATCH];                        // parity buffers
__device__ int   g_hflag[GW];   // monotonic within launch, reset to 1 by init barrier
__device__ int   g_aflag[GW];
__device__ int   g_arr[GW];     // init barrier (2-phase equality, leader = CTA 0)
__device__ int   g_rel;

// ---------------- f32x2 helpers ----------------
__device__ __forceinline__ ull packdup(float w) {
    ull r; unsigned u = __float_as_uint(w);
    asm("mov.b64 %0, {%1, %2};" : "=l"(r) : "r"(u), "r"(u));
    return r;
}
__device__ __forceinline__ ull pack2f(float a, float b) {
    ull r; asm("mov.b64 %0, {%1, %2};" : "=l"(r) : "f"(a), "f"(b));
    return r;
}
__device__ __forceinline__ float2 unpk(ull v) {
    float2 r; asm("mov.b64 {%0, %1}, %2;" : "=f"(r.x), "=f"(r.y) : "l"(v));
    return r;
}
__device__ __forceinline__ ull fma2(ull a, ull b, ull c) {
    ull d; asm("fma.rn.f32x2 %0, %1, %2, %3;" : "=l"(d) : "l"(a), "l"(b), "l"(c));
    return d;
}
__device__ __forceinline__ ull add2(ull a, ull b) {
    ull d; asm("add.rn.f32x2 %0, %1, %2;" : "=l"(d) : "l"(a), "l"(b));
    return d;
}

// ---------------- sync / DSMEM helpers ----------------
__device__ __forceinline__ unsigned s2u(const void* p) {
    unsigned a;
    asm("{ .reg .u64 t; cvta.to.shared.u64 t, %1; cvt.u32.u64 %0, t; }"
        : "=r"(a) : "l"(p));
    return a;
}
__device__ __forceinline__ void dsmem_st64(unsigned laddr, int rk, ull v) {
    unsigned ra;
    asm volatile("mapa.shared::cluster.u32 %0, %1, %2;" : "=r"(ra) : "r"(laddr), "r"(rk));
    asm volatile("st.shared::cluster.b64 [%0], %1;" :: "r"(ra), "l"(v) : "memory");
}
__device__ __forceinline__ void dsmem_st32(unsigned laddr, int rk, int v) {
    unsigned ra;
    asm volatile("mapa.shared::cluster.u32 %0, %1, %2;" : "=r"(ra) : "r"(laddr), "r"(rk));
    asm volatile("st.shared::cluster.b32 [%0], %1;" :: "r"(ra), "r"(v) : "memory");
}
__device__ __forceinline__ void fence_cluster() {
    asm volatile("fence.acq_rel.cluster;" ::: "memory");
}
__device__ __forceinline__ void barn(int id) {   // named barrier, 256 threads
    asm volatile("bar.sync %0, 256;" :: "r"(id) : "memory");
}

// ---------------------------------------------------------------------------
// Precompute GEMM: g_xw[t][j][b] = sum_i x[b][t][i]*W_ih[j][i] + b_ih[j]+b_hh[j]
// ---------------------------------------------------------------------------
__global__ __launch_bounds__(256) void xw_gemm(const float* __restrict__ x,
                                               const float* __restrict__ W_ih,
                                               const float* __restrict__ b_ih,
                                               const float* __restrict__ b_hh) {
    __shared__ float As[16][68];
    __shared__ float Bs[16][68];

    const int r0 = blockIdx.x * 64;
    const int j0 = blockIdx.y * 64;
    const int tx = threadIdx.x & 15;
    const int ty = threadIdx.x >> 4;

    float acc[4][4] = {};

    for (int k0 = 0; k0 < IDIM; k0 += 16) {
#pragma unroll
        for (int m = 0; m < 4; ++m) {
            int lin = threadIdx.x + 256 * m;
            int rr = lin >> 4, kk = lin & 15;
            As[kk][rr] = x[(size_t)(r0 + rr) * IDIM + k0 + kk];
            Bs[kk][rr] = W_ih[(size_t)(j0 + rr) * IDIM + k0 + kk];
        }
        __syncthreads();
#pragma unroll
        for (int kk = 0; kk < 16; ++kk) {
            float4 av = *(const float4*)&As[kk][ty * 4];
            float4 bv = *(const float4*)&Bs[kk][tx * 4];
            float af[4] = {av.x, av.y, av.z, av.w};
            float bf[4] = {bv.x, bv.y, bv.z, bv.w};
#pragma unroll
            for (int i = 0; i < 4; ++i)
#pragma unroll
                for (int j = 0; j < 4; ++j)
                    acc[i][j] += af[i] * bf[j];
        }
        __syncthreads();
    }

#pragma unroll
    for (int i = 0; i < 4; ++i) {
        int r = r0 + ty * 4 + i;
        int t = r & (S_LEN - 1);
        int b = r >> 9;
#pragma unroll
        for (int j = 0; j < 4; ++j) {
            int col = j0 + tx * 4 + j;
            g_xw[((size_t)t * HDIM + col) * BATCH + b] = acc[i][j] + b_ih[col] + b_hh[col];
        }
    }
}

// ---------------------------------------------------------------------------
// Persistent warp-specialized RNN kernel.
//   h-pipe (warps 0-7),  rounds r=0..S-1: h_{r+1} = tanh(xw_r + h_r W_hh^T) -> g_hall[r+1]
//   a-pipe (warps 8-15), rounds r=0..S:   a_r = tanh(h_r W_ya^T + a_{r-1} W_aa^T + b)
//                                          (round 0 stores a_0 = 0; round S emits out)
// Flags: reset to 1 by the init barrier; round r publishes r+2; polls use >= r+1
// (monotonic within launch -> skew-proof). Init barrier: 2-phase leader equality
// (values 1,2; resting stale value 2 cannot alias probe 1 on replay).
// ---------------------------------------------------------------------------
__global__ __launch_bounds__(NT, 1) __cluster_dims__(4, 1, 1)
void rnn_all(const float* __restrict__ W_hh,
             const float* __restrict__ W_ya,
             const float* __restrict__ b_ya,
             const float* __restrict__ W_aa,
             const float* __restrict__ b_aa,
             float* __restrict__ out) {
    extern __shared__ char smem[];
    ull* wHd   = (ull*)(smem + OFF_WHD);
    ull* wAd   = (ull*)(smem + OFF_WAD);
    ull* redH  = (ull*)(smem + OFF_REDH);
    ull* redA  = (ull*)(smem + OFF_REDA);
    ull* mboxH = (ull*)(smem + OFF_MBOXH);
    ull* mboxA = (ull*)(smem + OFF_MBOXA);
    volatile int* mbfH = (volatile int*)(smem + OFF_MBFH);
    volatile int* mbfA = (volatile int*)(smem + OFF_MBFA);

    const int tid = threadIdx.x;
    const int bid = blockIdx.x;
    const int cl  = bid >> 2;
    const int ks  = bid & 3;
    const int c0  = cl * 16;

    const unsigned mboxH_u = s2u((const void*)mboxH);
    const unsigned mboxA_u = s2u((const void*)mboxA);
    const unsigned mbfH_u  = s2u((const void*)mbfH);
    const unsigned mbfA_u  = s2u((const void*)mbfA);

    // ---- init: zero h_0 and a_{-1}, load weights, reset own flags ----
    for (int i = bid * NT + tid; i < HDIM * BATCH / 2; i += GW * NT) {
        ((ull*)g_hall)[i] = 0ull;   // h_0 = 0
        ((ull*)g_a[1])[i] = 0ull;   // a_{-1} slot (finite, never used numerically)
    }
    for (int i = tid; i < 128 * 16; i += NT) {
        int k = i >> 4, c = i & 15;
        wHd[i] = packdup(__ldg(&W_hh[(size_t)(c0 + c) * HDIM + ks * 128 + k]));
    }
    for (int i = tid; i < 256 * 16; i += NT) {
        int k = i >> 4, c = i & 15;
        float v = (ks < 2) ? __ldg(&W_ya[(size_t)(c0 + c) * HDIM + ks * 256 + k])
                           : __ldg(&W_aa[(size_t)(c0 + c) * EDIM + (ks - 2) * 256 + k]);
        wAd[i] = packdup(v);
    }
    if (tid < 4) { mbfH[tid] = 0; mbfA[tid] = 0; }
    if (tid == 0) {
        *(volatile int*)&g_hflag[bid] = 1;
        *(volatile int*)&g_aflag[bid] = 1;
    }
    __threadfence();
    __syncthreads();

    // ---- replay-safe 2-phase init barrier (leader = CTA 0) ----
#pragma unroll
    for (int v = 1; v <= 2; ++v) {
        if (tid == 0) { __threadfence(); *(volatile int*)&g_arr[bid] = v; }
        if (bid == 0) {
            if (tid < GW) { while (*(volatile int*)&g_arr[tid] != v) { } }
            __syncthreads();
            if (tid == 0) { __threadfence(); *(volatile int*)&g_rel = v; }
        }
        if (tid == 0) { while (*(volatile int*)&g_rel != v) { } __threadfence(); }
        __syncthreads();
    }

    if (tid < 256) {
        // ================= h-pipeline (warps 0-7) =================
        const int w   = tid >> 5;
        const int bp  = tid & 31;
        const int jC  = (tid >> 5) & 3;     // combine col slot (tid<128)
        const int bpC = tid & 31;
        const int cC  = c0 + ks * 4 + jC;
        const int ccR = tid >> 5;           // reduce col base

        for (int r = 0; r < S_LEN; ++r) {
            // xw prefetch (independent of h_r -> issue before poll)
            ull xwv = 0ull;
            if (tid < 128)
                xwv = __ldcg((const ull*)(g_xw + ((size_t)r * HDIM + cC) * BATCH) + bpC);

            // wait h_r published by ALL CTAs (monotonic >=)
            if (tid < 128) {
                volatile int* f = &g_hflag[tid];
                while (*f < r + 1) { }
                __threadfence();
            }
            barn(1);

            // h-GEMM: warp w covers k-slice of 16 in g_hall[r], all 16 cols
            {
                ull acc[16];
#pragma unroll
                for (int c = 0; c < 16; ++c) acc[c] = 0ull;
                const ull* hsrc = (const ull*)(g_hall + ((size_t)r * HDIM
                                  + ks * 128 + w * 16) * BATCH) + bp;
                const ull* whr  = wHd + (w * 16) * 16;
#pragma unroll
                for (int kk = 0; kk < 16; ++kk) {
                    ull hv = __ldcg(hsrc + kk * 32);
                    const ulonglong2* wp = (const ulonglong2*)(whr + kk * 16);
#pragma unroll
                    for (int cp = 0; cp < 8; ++cp) {
                        ulonglong2 w2 = wp[cp];
                        acc[2 * cp]     = fma2(hv, w2.x, acc[2 * cp]);
                        acc[2 * cp + 1] = fma2(hv, w2.y, acc[2 * cp + 1]);
                    }
                }
#pragma unroll
                for (int c = 0; c < 16; ++c) redH[(w * 16 + c) * 32 + bp] = acc[c];
            }
            barn(1);

            // reduce over 8 warps + DSMEM scatter
#pragma unroll
            for (int i = 0; i < 2; ++i) {
                int cc = ccR + i * 8;
                ull s = redH[cc * 32 + bp];
#pragma unroll
                for (int ww = 1; ww < 8; ++ww) s = add2(s, redH[(ww * 16 + cc) * 32 + bp]);
                unsigned la = mboxH_u + (((ks * 4 + (cc & 3)) * 32 + bp) << 3);
                dsmem_st64(la, cc >> 2, s);
            }
            fence_cluster();
            barn(1);
            if (tid < 4) dsmem_st32(mbfH_u + ks * 4, tid, r + 2);

            // wait all 4 ranks' slices (per-slot equality is overwrite-safe here:
            // producers can't reach round r+1 until this CTA publishes flag r+2)
            if (tid < 4) { while (mbfH[tid] != r + 2) { } }
            fence_cluster();
            barn(1);
            if (tid < 128) {
                ull v =      mboxH[(0 * 4 + jC) * 32 + bpC];
                v = add2(v,  mboxH[(1 * 4 + jC) * 32 + bpC]);
                v = add2(v,  mboxH[(2 * 4 + jC) * 32 + bpC]);
                v = add2(v,  mboxH[(3 * 4 + jC) * 32 + bpC]);
                v = add2(v, xwv);
                float2 f = unpk(v);
                f.x = tanhf(f.x); f.y = tanhf(f.y);
                *(ull*)(g_hall + ((size_t)(r + 1) * HDIM + cC) * BATCH + 2 * bpC)
                    = pack2f(f.x, f.y);
                __threadfence();
            }
            barn(1);
            if (tid == 0) *(volatile int*)&g_hflag[bid] = r + 2;
        }
    } else {
        // ================= a-pipeline (warps 8-15) =================
        const int gt  = tid - 256;
        const int w   = gt >> 5;
        const int bp  = gt & 31;
        const int jC  = (gt >> 5) & 3;
        const int bpC = gt & 31;
        const int cC  = c0 + ks * 4 + jC;
        const int ccR = gt >> 5;
        const float biasC = b_ya[cC] + b_aa[cC];

        for (int r = 0; r <= S_LEN; ++r) {
            const int p = r & 1;

            // wait h_r (flag >= r+1) and a_{r-1} (flag >= r+1)
            if (gt < 128) {
                volatile int* f = &g_hflag[gt];
                while (*f < r + 1) { }
                __threadfence();
            } else {
                volatile int* f = &g_aflag[gt - 128];
                while (*f < r + 1) { }
                __threadfence();
            }
            barn(2);

            // a-GEMM: warp w covers k-slice of 32 within this CTA's 256-k slice
            {
                ull acc[16];
#pragma unroll
                for (int c = 0; c < 16; ++c) acc[c] = 0ull;
                const float* sA = (ks < 2)
                    ? (g_hall + ((size_t)r * HDIM + ks * 256 + w * 32) * BATCH)
                    : (g_a[p ^ 1] + ((ks - 2) * 256 + w * 32) * BATCH);
                const ull* asrc = (const ull*)sA + bp;
                const ull* war  = wAd + (w * 32) * 16;
#pragma unroll
                for (int kk = 0; kk < 32; ++kk) {
                    ull hv = __ldcg(asrc + kk * 32);
                    const ulonglong2* wp = (const ulonglong2*)(war + kk * 16);
#pragma unroll
                    for (int cp = 0; cp < 8; ++cp) {
                        ulonglong2 w2 = wp[cp];
                        acc[2 * cp]     = fma2(hv, w2.x, acc[2 * cp]);
                        acc[2 * cp + 1] = fma2(hv, w2.y, acc[2 * cp + 1]);
                    }
                }
#pragma unroll
                for (int c = 0; c < 16; ++c) redA[(w * 16 + c) * 32 + bp] = acc[c];
            }
            barn(2);

            // reduce + DSMEM scatter
#pragma unroll
            for (int i = 0; i < 2; ++i) {
                int cc = ccR + i * 8;
                ull s = redA[cc * 32 + bp];
#pragma unroll
                for (int ww = 1; ww < 8; ++ww) s = add2(s, redA[(ww * 16 + cc) * 32 + bp]);
                unsigned la = mboxA_u + (((ks * 4 + (cc & 3)) * 32 + bp) << 3);
                dsmem_st64(la, cc >> 2, s);
            }
            fence_cluster();
            barn(2);
            if (gt < 4) dsmem_st32(mbfA_u + ks * 4, gt, r + 2);

            if (gt < 4) { while (mbfA[gt] != r + 2) { } }
            fence_cluster();
            barn(2);
            if (gt < 128) {
                float2 f;
                if (r == 0) {
                    f.x = 0.f; f.y = 0.f;                    // a_0 = 0
                } else {
                    ull v =      mboxA[(0 * 4 + jC) * 32 + bpC];
                    v = add2(v,  mboxA[(1 * 4 + jC) * 32 + bpC]);
                    v = add2(v,  mboxA[(2 * 4 + jC) * 32 + bpC]);
                    v = add2(v,  mboxA[(3 * 4 + jC) * 32 + bpC]);
                    f = unpk(v);
                    f.x = tanhf(f.x + biasC); f.y = tanhf(f.y + biasC);
                }
                *(ull*)(g_a[p] + cC * BATCH + 2 * bpC) = pack2f(f.x, f.y);
                if (r == S_LEN) {
                    out[(size_t)(2 * bpC) * EDIM + cC]     = f.x;
                    out[(size_t)(2 * bpC + 1) * EDIM + cC] = f.y;
                }
                __threadfence();
            }
            barn(2);
            if (gt == 0) *(volatile int*)&g_aflag[bid] = r + 2;
        }
    }

    // clean join of both pipes before any CTA of the cluster exits
    __syncthreads();
    asm volatile("barrier.cluster.arrive.aligned;" ::: "memory");
    asm volatile("barrier.cluster.wait.aligned;" ::: "memory");
}

// ---------------------------------------------------------------------------
extern "C" void kernel_launch(void* const* d_in, const int* in_sizes, int n_in,
                              void* d_out, int out_size) {
    const float* x    = (const float*)d_in[0];
    const float* W_ih = (const float*)d_in[1];
    const float* W_hh = (const float*)d_in[2];
    const float* b_ih = (const float*)d_in[3];
    const float* b_hh = (const float*)d_in[4];
    const float* W_ya = (const float*)d_in[5];
    const float* b_ya = (const float*)d_in[6];
    const float* W_aa = (const float*)d_in[7];
    const float* b_aa = (const float*)d_in[8];
    float* out = (float*)d_out;

    cudaFuncSetAttribute(rnn_all,
                         cudaFuncAttributeMaxDynamicSharedMemorySize, SMEM_BYTES);

    xw_gemm<<<dim3((BATCH * S_LEN) / 64, HDIM / 64), 256>>>(x, W_ih, b_ih, b_hh);
    rnn_all<<<GW, NT, SMEM_BYTES>>>(W_hh, W_ya, b_ya, W_aa, b_aa, out);
}

// round 11
// speedup vs baseline: 1.2183x; 1.2183x over previous
#include <cuda_runtime.h>
#include <math.h>
#include <stdint.h>
#include <stddef.h>

typedef unsigned long long ull;

// Problem dims
static constexpr int S_LEN = 512;
static constexpr int BATCH = 64;
static constexpr int IDIM  = 256;
static constexpr int HDIM  = 512;
static constexpr int EDIM  = 512;

// 128 worker CTAs = 32 clusters x 4 k-split ranks, merged h+a round, 1 sync/round
static constexpr int GW  = 128;
static constexpr int NT  = 512;   // 16 warps

// smem byte offsets
static constexpr int OFF_WHD   = 0;        // 128k x 16c ull dup   = 16384
static constexpr int OFF_WAD   = 16384;    // 256k x 16c ull dup   = 32768
static constexpr int OFF_REDH  = 49152;    // 16w x 16c x 32bp ull = 65536
static constexpr int OFF_REDA  = 114688;   // 16w x 16c x 32bp ull = 65536
static constexpr int OFF_MBOXH = 180224;   // 4src x 4c x 32bp ull = 4096
static constexpr int OFF_MBOXA = 184320;   // 4096
static constexpr int OFF_MBF   = 188416;   // 4 ints
static constexpr int SMEM_BYTES = 188448;

// Device scratch (allocation-free rule)
__device__ float g_xw[(size_t)S_LEN * HDIM * BATCH];  // [t][c][b]
__device__ float g_h[2][HDIM * BATCH];                // [c][b] parity buffers
__device__ float g_a[2][EDIM * BATCH];
__device__ int   g_flag[GW];    // per-CTA round flag, monotonic within launch
__device__ int   g_arr[GW];     // init barrier (2-phase equality, leader = CTA 0)
__device__ int   g_rel;

// ---------------- f32x2 helpers ----------------
__device__ __forceinline__ ull packdup(float w) {
    ull r; unsigned u = __float_as_uint(w);
    asm("mov.b64 %0, {%1, %2};" : "=l"(r) : "r"(u), "r"(u));
    return r;
}
__device__ __forceinline__ ull pack2f(float a, float b) {
    ull r; asm("mov.b64 %0, {%1, %2};" : "=l"(r) : "f"(a), "f"(b));
    return r;
}
__device__ __forceinline__ float2 unpk(ull v) {
    float2 r; asm("mov.b64 {%0, %1}, %2;" : "=f"(r.x), "=f"(r.y) : "l"(v));
    return r;
}
__device__ __forceinline__ ull fma2(ull a, ull b, ull c) {
    ull d; asm("fma.rn.f32x2 %0, %1, %2, %3;" : "=l"(d) : "l"(a), "l"(b), "l"(c));
    return d;
}
__device__ __forceinline__ ull add2(ull a, ull b) {
    ull d; asm("add.rn.f32x2 %0, %1, %2;" : "=l"(d) : "l"(a), "l"(b));
    return d;
}

// ---------------- sync / DSMEM helpers ----------------
__device__ __forceinline__ unsigned s2u(const void* p) {
    unsigned a;
    asm("{ .reg .u64 t; cvta.to.shared.u64 t, %1; cvt.u32.u64 %0, t; }"
        : "=r"(a) : "l"(p));
    return a;
}
__device__ __forceinline__ void dsmem_st64(unsigned laddr, int rk, ull v) {
    unsigned ra;
    asm volatile("mapa.shared::cluster.u32 %0, %1, %2;" : "=r"(ra) : "r"(laddr), "r"(rk));
    asm volatile("st.shared::cluster.b64 [%0], %1;" :: "r"(ra), "l"(v) : "memory");
}
__device__ __forceinline__ void dsmem_st32(unsigned laddr, int rk, int v) {
    unsigned ra;
    asm volatile("mapa.shared::cluster.u32 %0, %1, %2;" : "=r"(ra) : "r"(laddr), "r"(rk));
    asm volatile("st.shared::cluster.b32 [%0], %1;" :: "r"(ra), "r"(v) : "memory");
}
__device__ __forceinline__ void fence_cluster() {
    asm volatile("fence.acq_rel.cluster;" ::: "memory");
}

// ---------------------------------------------------------------------------
// Precompute GEMM: g_xw[t][j][b] = sum_i x[b][t][i]*W_ih[j][i] + b_ih[j]+b_hh[j]
// ---------------------------------------------------------------------------
__global__ __launch_bounds__(256) void xw_gemm(const float* __restrict__ x,
                                               const float* __restrict__ W_ih,
                                               const float* __restrict__ b_ih,
                                               const float* __restrict__ b_hh) {
    __shared__ float As[16][68];
    __shared__ float Bs[16][68];

    const int r0 = blockIdx.x * 64;
    const int j0 = blockIdx.y * 64;
    const int tx = threadIdx.x & 15;
    const int ty = threadIdx.x >> 4;

    float acc[4][4] = {};

    for (int k0 = 0; k0 < IDIM; k0 += 16) {
#pragma unroll
        for (int m = 0; m < 4; ++m) {
            int lin = threadIdx.x + 256 * m;
            int rr = lin >> 4, kk = lin & 15;
            As[kk][rr] = x[(size_t)(r0 + rr) * IDIM + k0 + kk];
            Bs[kk][rr] = W_ih[(size_t)(j0 + rr) * IDIM + k0 + kk];
        }
        __syncthreads();
#pragma unroll
        for (int kk = 0; kk < 16; ++kk) {
            float4 av = *(const float4*)&As[kk][ty * 4];
            float4 bv = *(const float4*)&Bs[kk][tx * 4];
            float af[4] = {av.x, av.y, av.z, av.w};
            float bf[4] = {bv.x, bv.y, bv.z, bv.w};
#pragma unroll
            for (int i = 0; i < 4; ++i)
#pragma unroll
                for (int j = 0; j < 4; ++j)
                    acc[i][j] += af[i] * bf[j];
        }
        __syncthreads();
    }

#pragma unroll
    for (int i = 0; i < 4; ++i) {
        int r = r0 + ty * 4 + i;
        int t = r & (S_LEN - 1);
        int b = r >> 9;
#pragma unroll
        for (int j = 0; j < 4; ++j) {
            int col = j0 + tx * 4 + j;
            g_xw[((size_t)t * HDIM + col) * BATCH + b] = acc[i][j] + b_ih[col] + b_hh[col];
        }
    }
}

// ---------------------------------------------------------------------------
// Persistent merged-round RNN kernel (one global sync per round).
// Round r (0..S): h_{r+1} = tanh(xw_r + h_r W_hh^T)            [r < S]
//                 a_r     = tanh(h_r W_ya^T + a_{r-1} W_aa^T + b) [a_0 = 0; r==S -> out]
// Flags: reset to 1 by init barrier; round r publishes r+2; polls use >= r+1.
// ---------------------------------------------------------------------------
__global__ __launch_bounds__(NT, 1) __cluster_dims__(4, 1, 1)
void rnn_all(const float* __restrict__ W_hh,
             const float* __restrict__ W_ya,
             const float* __restrict__ b_ya,
             const float* __restrict__ W_aa,
             const float* __restrict__ b_aa,
             float* __restrict__ out) {
    extern __shared__ char smem[];
    ull* wHd   = (ull*)(smem + OFF_WHD);
    ull* wAd   = (ull*)(smem + OFF_WAD);
    ull* redH  = (ull*)(smem + OFF_REDH);
    ull* redA  = (ull*)(smem + OFF_REDA);
    ull* mboxH = (ull*)(smem + OFF_MBOXH);
    ull* mboxA = (ull*)(smem + OFF_MBOXA);
    volatile int* mbf = (volatile int*)(smem + OFF_MBF);

    const int tid = threadIdx.x;
    const int bid = blockIdx.x;
    const int cl  = bid >> 2;
    const int ks  = bid & 3;
    const int c0  = cl * 16;

    const unsigned mboxH_u = s2u((const void*)mboxH);
    const unsigned mboxA_u = s2u((const void*)mboxA);
    const unsigned mbf_u   = s2u((const void*)mbf);

    const int w  = tid >> 5;         // warp 0..15
    const int bp = tid & 31;         // batch-pair lane

    // combine roles (first 256 threads)
    const int phC = (tid >> 7) & 1;      // 0: h-cols, 1: a-cols
    const int jC  = (tid >> 5) & 3;      // owned col slot 0..3
    const int bpC = tid & 31;
    const int cC  = c0 + ks * 4 + jC;
    const float biasC = (tid < 256 && phC == 1) ? (b_ya[cC] + b_aa[cC]) : 0.f;

    // reduce roles: one h-output and one a-output per thread
    const int cR  = tid >> 5;            // 0..15
    const int bpR = tid & 31;

    // ---- init: zero state, load weights, reset flags ----
    for (int i = bid * NT + tid; i < HDIM * BATCH / 2; i += GW * NT) {
        ((ull*)g_h[0])[i] = 0ull;   // h_0 = 0
        ((ull*)g_a[1])[i] = 0ull;   // a_{-1} slot (finite, never used numerically)
    }
    for (int i = tid; i < 128 * 16; i += NT) {
        int k = i >> 4, c = i & 15;
        wHd[i] = packdup(__ldg(&W_hh[(size_t)(c0 + c) * HDIM + ks * 128 + k]));
    }
    for (int i = tid; i < 256 * 16; i += NT) {
        int k = i >> 4, c = i & 15;
        float v = (ks < 2) ? __ldg(&W_ya[(size_t)(c0 + c) * HDIM + ks * 256 + k])
                           : __ldg(&W_aa[(size_t)(c0 + c) * EDIM + (ks - 2) * 256 + k]);
        wAd[i] = packdup(v);
    }
    if (tid < 4) mbf[tid] = 0;
    if (tid == 0) *(volatile int*)&g_flag[bid] = 1;
    __threadfence();
    __syncthreads();

    // ---- replay-safe 2-phase init barrier (leader = CTA 0) ----
#pragma unroll
    for (int v = 1; v <= 2; ++v) {
        if (tid == 0) { __threadfence(); *(volatile int*)&g_arr[bid] = v; }
        if (bid == 0) {
            if (tid < GW) { while (*(volatile int*)&g_arr[tid] != v) { } }
            __syncthreads();
            if (tid == 0) { __threadfence(); *(volatile int*)&g_rel = v; }
        }
        if (tid == 0) { while (*(volatile int*)&g_rel != v) { } __threadfence(); }
        __syncthreads();
    }

    for (int r = 0; r <= S_LEN; ++r) {
        const int p = r & 1;

        // xw prefetch (independent of state -> issue before poll)
        ull xwv = 0ull;
        if (tid < 128 && r < S_LEN)
            xwv = __ldcg((const ull*)(g_xw + ((size_t)r * HDIM + cC) * BATCH) + bpC);

        // ---- single-hop distributed barrier: all CTAs at round r ----
        if (tid < GW) {
            volatile int* f = &g_flag[tid];
            while (*f < r + 1) { }
            __threadfence();
        }
        __syncthreads();

        // ---- h-GEMM: warp w covers 8-k slice of this CTA's 128-k range ----
        ull accH[16];
        {
#pragma unroll
            for (int c = 0; c < 16; ++c) accH[c] = 0ull;
            const ull* hsrc = (const ull*)(g_h[p] + (ks * 128 + w * 8) * BATCH) + bp;
            const ull* whr  = wHd + (w * 8) * 16;
#pragma unroll
            for (int kk = 0; kk < 8; ++kk) {
                ull hv = __ldcg(hsrc + kk * 32);
                const ulonglong2* wp = (const ulonglong2*)(whr + kk * 16);
#pragma unroll
                for (int cp = 0; cp < 8; ++cp) {
                    ulonglong2 w2 = wp[cp];
                    accH[2 * cp]     = fma2(hv, w2.x, accH[2 * cp]);
                    accH[2 * cp + 1] = fma2(hv, w2.y, accH[2 * cp + 1]);
                }
            }
        }

        // ---- a-GEMM: warp w covers 16-k slice of this CTA's 256-k range ----
        ull accA[16];
        {
#pragma unroll
            for (int c = 0; c < 16; ++c) accA[c] = 0ull;
            const float* sA = (ks < 2) ? (g_h[p] + (ks * 256 + w * 16) * BATCH)
                                       : (g_a[p ^ 1] + ((ks - 2) * 256 + w * 16) * BATCH);
            const ull* asrc = (const ull*)sA + bp;
            const ull* war  = wAd + (w * 16) * 16;
#pragma unroll
            for (int kk = 0; kk < 16; ++kk) {
                ull hv = __ldcg(asrc + kk * 32);
                const ulonglong2* wp = (const ulonglong2*)(war + kk * 16);
#pragma unroll
                for (int cp = 0; cp < 8; ++cp) {
                    ulonglong2 w2 = wp[cp];
                    accA[2 * cp]     = fma2(hv, w2.x, accA[2 * cp]);
                    accA[2 * cp + 1] = fma2(hv, w2.y, accA[2 * cp + 1]);
                }
            }
        }

        // ---- store both partial sets, one sync, reduce+scatter both ----
#pragma unroll
        for (int c = 0; c < 16; ++c) redH[(w * 16 + c) * 32 + bp] = accH[c];
#pragma unroll
        for (int c = 0; c < 16; ++c) redA[(w * 16 + c) * 32 + bp] = accA[c];
        __syncthreads();
        {
            ull sH = redH[cR * 32 + bpR];
            ull sAc = redA[cR * 32 + bpR];
#pragma unroll
            for (int ww = 1; ww < 16; ++ww) {
                sH  = add2(sH,  redH[(ww * 16 + cR) * 32 + bpR]);
                sAc = add2(sAc, redA[(ww * 16 + cR) * 32 + bpR]);
            }
            unsigned off = (((ks * 4 + (cR & 3)) * 32 + bpR) << 3);
            dsmem_st64(mboxH_u + off, cR >> 2, sH);
            dsmem_st64(mboxA_u + off, cR >> 2, sAc);
        }
        fence_cluster();
        __syncthreads();
        if (tid < 4) dsmem_st32(mbf_u + ks * 4, tid, r + 2);

        // wait all 4 ranks' slices (equality safe: global flag chain orders rounds)
        if (tid < 4) { while (mbf[tid] != r + 2) { } }
        fence_cluster();
        __syncthreads();

        // ---- combine: sum 4 k-split partials, activate, publish ----
        if (tid < 256) {
            if (phC == 0) {
                if (r < S_LEN) {
                    ull v =      mboxH[(0 * 4 + jC) * 32 + bpC];
                    v = add2(v,  mboxH[(1 * 4 + jC) * 32 + bpC]);
                    v = add2(v,  mboxH[(2 * 4 + jC) * 32 + bpC]);
                    v = add2(v,  mboxH[(3 * 4 + jC) * 32 + bpC]);
                    v = add2(v, xwv);
                    float2 f = unpk(v);
                    f.x = tanhf(f.x); f.y = tanhf(f.y);
                    *(ull*)(g_h[p ^ 1] + cC * BATCH + 2 * bpC) = pack2f(f.x, f.y);
                }
            } else {
                float2 f;
                if (r == 0) {
                    f.x = 0.f; f.y = 0.f;                    // a_0 = 0
                } else {
                    ull v =      mboxA[(0 * 4 + jC) * 32 + bpC];
                    v = add2(v,  mboxA[(1 * 4 + jC) * 32 + bpC]);
                    v = add2(v,  mboxA[(2 * 4 + jC) * 32 + bpC]);
                    v = add2(v,  mboxA[(3 * 4 + jC) * 32 + bpC]);
                    f = unpk(v);
                    f.x = tanhf(f.x + biasC); f.y = tanhf(f.y + biasC);
                }
                *(ull*)(g_a[p] + cC * BATCH + 2 * bpC) = pack2f(f.x, f.y);
                if (r == S_LEN) {
                    out[(size_t)(2 * bpC) * EDIM + cC]     = f.x;
                    out[(size_t)(2 * bpC + 1) * EDIM + cC] = f.y;
                }
            }
        }
        __syncthreads();
        if (tid == 0 && r < S_LEN) {
            __threadfence();
            *(volatile int*)&g_flag[bid] = r + 2;
        }
    }

    // clean exit: no CTA leaves while cluster peers may still scatter to it
    __syncthreads();
    asm volatile("barrier.cluster.arrive.aligned;" ::: "memory");
    asm volatile("barrier.cluster.wait.aligned;" ::: "memory");
}

// ---------------------------------------------------------------------------
extern "C" void kernel_launch(void* const* d_in, const int* in_sizes, int n_in,
                              void* d_out, int out_size) {
    const float* x    = (const float*)d_in[0];
    const float* W_ih = (const float*)d_in[1];
    const float* W_hh = (const float*)d_in[2];
    const float* b_ih = (const float*)d_in[3];
    const float* b_hh = (const float*)d_in[4];
    const float* W_ya = (const float*)d_in[5];
    const float* b_ya = (const float*)d_in[6];
    const float* W_aa = (const float*)d_in[7];
    const float* b_aa = (const float*)d_in[8];
    float* out = (float*)d_out;

    cudaFuncSetAttribute(rnn_all,
                         cudaFuncAttributeMaxDynamicSharedMemorySize, SMEM_BYTES);

    xw_gemm<<<dim3((BATCH * S_LEN) / 64, HDIM / 64), 256>>>(x, W_ih, b_ih, b_hh);
    rnn_all<<<GW, NT, SMEM_BYTES>>>(W_hh, W_ya, b_ya, W_aa, b_aa, out);
}

// round 12
// speedup vs baseline: 1.7256x; 1.4163x over previous
#include <cuda_runtime.h>
#include <math.h>
#include <stdint.h>
#include <stddef.h>

typedef unsigned long long ull;

// Problem dims
static constexpr int S_LEN = 512;
static constexpr int BATCH = 64;
static constexpr int IDIM  = 256;
static constexpr int HDIM  = 512;
static constexpr int EDIM  = 512;

// Grid: 128 worker CTAs (32 clusters x 4 k-split ranks) + 1 leader CTA (+3 idle)
static constexpr int GW  = 128;
static constexpr int G   = 132;
static constexpr int NT  = 512;   // warps 0-7: h-partials, warps 8-15: a-partials

// smem byte offsets
static constexpr int OFF_WHD   = 0;        // 128k x 16c ull dup  = 16384
static constexpr int OFF_WAD   = 16384;    // 256k x 16c ull dup  = 32768
static constexpr int OFF_REDH  = 49152;    // 8w x 16c x 32bp ull = 32768
static constexpr int OFF_REDA  = 81920;    // 8w x 16c x 32bp ull = 32768
static constexpr int OFF_MBOXH = 114688;   // 4src x 4c x 32bp ull = 4096
static constexpr int OFF_MBOXA = 118784;   // 4096
static constexpr int OFF_MBF   = 122880;   // 4 ints
static constexpr int SMEM_BYTES = 122912;

// Device scratch (allocation-free rule)
__device__ float g_xw[(size_t)S_LEN * HDIM * BATCH];  // [t][c][b]
__device__ float g_h[2][HDIM * BATCH];                // [c][b] parity buffers
__device__ float g_a[2][EDIM * BATCH];
__device__ int   g_arr[GW];   // worker arrive flags (equality, leader-paced)
__device__ int   g_rel;       // leader release word

// ---------------- f32x2 helpers ----------------
__device__ __forceinline__ ull packdup(float w) {
    ull r; unsigned u = __float_as_uint(w);
    asm("mov.b64 %0, {%1, %2};" : "=l"(r) : "r"(u), "r"(u));
    return r;
}
__device__ __forceinline__ ull pack2f(float a, float b) {
    ull r; asm("mov.b64 %0, {%1, %2};" : "=l"(r) : "f"(a), "f"(b));
    return r;
}
__device__ __forceinline__ float2 unpk(ull v) {
    float2 r; asm("mov.b64 {%0, %1}, %2;" : "=f"(r.x), "=f"(r.y) : "l"(v));
    return r;
}
__device__ __forceinline__ ull fma2(ull a, ull b, ull c) {
    ull d; asm("fma.rn.f32x2 %0, %1, %2, %3;" : "=l"(d) : "l"(a), "l"(b), "l"(c));
    return d;
}
__device__ __forceinline__ ull add2(ull a, ull b) {
    ull d; asm("add.rn.f32x2 %0, %1, %2;" : "=l"(d) : "l"(a), "l"(b));
    return d;
}

// ---------------- sync / DSMEM helpers ----------------
__device__ __forceinline__ unsigned s2u(const void* p) {
    unsigned a;
    asm("{ .reg .u64 t; cvta.to.shared.u64 t, %1; cvt.u32.u64 %0, t; }"
        : "=r"(a) : "l"(p));
    return a;
}
__device__ __forceinline__ void dsmem_st64(unsigned laddr, int rk, ull v) {
    unsigned ra;
    asm volatile("mapa.shared::cluster.u32 %0, %1, %2;" : "=r"(ra) : "r"(laddr), "r"(rk));
    asm volatile("st.shared::cluster.b64 [%0], %1;" :: "r"(ra), "l"(v) : "memory");
}
__device__ __forceinline__ void dsmem_st32(unsigned laddr, int rk, int v) {
    unsigned ra;
    asm volatile("mapa.shared::cluster.u32 %0, %1, %2;" : "=r"(ra) : "r"(laddr), "r"(rk));
    asm volatile("st.shared::cluster.b32 [%0], %1;" :: "r"(ra), "r"(v) : "memory");
}
__device__ __forceinline__ void fence_cluster() {
    asm volatile("fence.acq_rel.cluster;" ::: "memory");
}

// Leader-paced equality barrier (R6-proven; replay-safe: values strictly 1..S+1)
__device__ __forceinline__ void worker_barrier(int bid, int v) {
    __syncthreads();
    if (threadIdx.x == 0) {
        __threadfence();
        *(volatile int*)&g_arr[bid] = v;
        while (*(volatile int*)&g_rel != v) { }
        __threadfence();
    }
    __syncthreads();
}

// ---------------------------------------------------------------------------
// Precompute GEMM: g_xw[t][j][b] = sum_i x[b][t][i]*W_ih[j][i] + b_ih[j]+b_hh[j]
// ---------------------------------------------------------------------------
__global__ __launch_bounds__(256) void xw_gemm(const float* __restrict__ x,
                                               const float* __restrict__ W_ih,
                                               const float* __restrict__ b_ih,
                                               const float* __restrict__ b_hh) {
    __shared__ float As[16][68];
    __shared__ float Bs[16][68];

    const int r0 = blockIdx.x * 64;
    const int j0 = blockIdx.y * 64;
    const int tx = threadIdx.x & 15;
    const int ty = threadIdx.x >> 4;

    float acc[4][4] = {};

    for (int k0 = 0; k0 < IDIM; k0 += 16) {
#pragma unroll
        for (int m = 0; m < 4; ++m) {
            int lin = threadIdx.x + 256 * m;
            int rr = lin >> 4, kk = lin & 15;
            As[kk][rr] = x[(size_t)(r0 + rr) * IDIM + k0 + kk];
            Bs[kk][rr] = W_ih[(size_t)(j0 + rr) * IDIM + k0 + kk];
        }
        __syncthreads();
#pragma unroll
        for (int kk = 0; kk < 16; ++kk) {
            float4 av = *(const float4*)&As[kk][ty * 4];
            float4 bv = *(const float4*)&Bs[kk][tx * 4];
            float af[4] = {av.x, av.y, av.z, av.w};
            float bf[4] = {bv.x, bv.y, bv.z, bv.w};
#pragma unroll
            for (int i = 0; i < 4; ++i)
#pragma unroll
                for (int j = 0; j < 4; ++j)
                    acc[i][j] += af[i] * bf[j];
        }
        __syncthreads();
    }

#pragma unroll
    for (int i = 0; i < 4; ++i) {
        int r = r0 + ty * 4 + i;
        int t = r & (S_LEN - 1);
        int b = r >> 9;
#pragma unroll
        for (int j = 0; j < 4; ++j) {
            int col = j0 + tx * 4 + j;
            g_xw[((size_t)t * HDIM + col) * BATCH + b] = acc[i][j] + b_ih[col] + b_hh[col];
        }
    }
}

// ---------------------------------------------------------------------------
// Persistent merged-round RNN kernel (one leader barrier per round).
// Round r (0..S): h_{r+1} = tanh(xw_r + h_r W_hh^T)               [r < S]
//                 a_r     = tanh(h_r W_ya^T + a_{r-1} W_aa^T + b) [a_0 = 0; r==S -> out]
// ---------------------------------------------------------------------------
__global__ __launch_bounds__(NT, 1) __cluster_dims__(4, 1, 1)
void rnn_all(const float* __restrict__ W_hh,
             const float* __restrict__ W_ya,
             const float* __restrict__ b_ya,
             const float* __restrict__ W_aa,
             const float* __restrict__ b_aa,
             float* __restrict__ out) {
    extern __shared__ char smem[];
    ull* wHd   = (ull*)(smem + OFF_WHD);
    ull* wAd   = (ull*)(smem + OFF_WAD);
    ull* redH  = (ull*)(smem + OFF_REDH);
    ull* redA  = (ull*)(smem + OFF_REDA);
    ull* mboxH = (ull*)(smem + OFF_MBOXH);
    ull* mboxA = (ull*)(smem + OFF_MBOXA);
    volatile int* mbf = (volatile int*)(smem + OFF_MBF);

    const int tid = threadIdx.x;
    const int bid = blockIdx.x;

    // ---- leader CTA paces the grid barrier ----
    if (bid >= GW) {
        if (bid == GW) {
            for (int v = 1; v <= S_LEN + 1; ++v) {
                if (tid < GW) { while (*(volatile int*)&g_arr[tid] != v) { } }
                __syncthreads();
                if (tid == 0) { __threadfence(); *(volatile int*)&g_rel = v; }
                __syncthreads();
            }
        }
        return;
    }

    const int cl = bid >> 2;
    const int ks = bid & 3;
    const int c0 = cl * 16;

    const unsigned mboxH_u = s2u((const void*)mboxH);
    const unsigned mboxA_u = s2u((const void*)mboxA);
    const unsigned mbf_u   = s2u((const void*)mbf);

    const int w  = tid >> 5;         // warp 0..15
    const int bp = tid & 31;

    // combine roles (first 256 threads)
    const int phC = (tid >> 7) & 1;      // 0: h-cols, 1: a-cols
    const int jC  = (tid >> 5) & 3;
    const int bpC = tid & 31;
    const int cC  = c0 + ks * 4 + jC;
    const float biasC = (tid < 256 && phC == 1) ? (b_ya[cC] + b_aa[cC]) : 0.f;

    // ---- init: zero state, load weights, reset mbf ----
    for (int i = bid * NT + tid; i < HDIM * BATCH / 2; i += GW * NT) {
        ((ull*)g_h[0])[i] = 0ull;   // h_0 = 0
        ((ull*)g_a[1])[i] = 0ull;   // a_{-1} slot (finite, never used numerically)
    }
    for (int i = tid; i < 128 * 16; i += NT) {
        int k = i >> 4, c = i & 15;
        wHd[i] = packdup(__ldg(&W_hh[(size_t)(c0 + c) * HDIM + ks * 128 + k]));
    }
    for (int i = tid; i < 256 * 16; i += NT) {
        int k = i >> 4, c = i & 15;
        float v = (ks < 2) ? __ldg(&W_ya[(size_t)(c0 + c) * HDIM + ks * 256 + k])
                           : __ldg(&W_aa[(size_t)(c0 + c) * EDIM + (ks - 2) * 256 + k]);
        wAd[i] = packdup(v);
    }
    if (tid < 4) mbf[tid] = 0;

    // prefetch xw for round 0 (xw_gemm finished before this launch)
    ull xwv = 0ull;
    if (tid < 128)
        xwv = __ldcg((const ull*)(g_xw + ((size_t)0 * HDIM + cC) * BATCH) + bpC);

    worker_barrier(bid, 1);

    for (int r = 0; r <= S_LEN; ++r) {
        const int p = r & 1;

        // ---- partial GEMMs: warps 0-7 -> h, warps 8-15 -> a ----
        if (w < 8) {
            ull acc[16];
#pragma unroll
            for (int c = 0; c < 16; ++c) acc[c] = 0ull;
            const ull* hsrc = (const ull*)(g_h[p] + (ks * 128 + w * 16) * BATCH) + bp;
            const ull* whr  = wHd + (w * 16) * 16;
#pragma unroll
            for (int kk = 0; kk < 16; ++kk) {
                ull hv = __ldcg(hsrc + kk * 32);
                const ulonglong2* wp = (const ulonglong2*)(whr + kk * 16);
#pragma unroll
                for (int cp = 0; cp < 8; ++cp) {
                    ulonglong2 w2 = wp[cp];
                    acc[2 * cp]     = fma2(hv, w2.x, acc[2 * cp]);
                    acc[2 * cp + 1] = fma2(hv, w2.y, acc[2 * cp + 1]);
                }
            }
#pragma unroll
            for (int c = 0; c < 16; ++c) redH[(w * 16 + c) * 32 + bp] = acc[c];
        } else {
            const int aw = w - 8;
            ull acc[16];
#pragma unroll
            for (int c = 0; c < 16; ++c) acc[c] = 0ull;
            const float* sA = (ks < 2)
                ? (g_h[p] + (ks * 256 + aw * 32) * BATCH)
                : (g_a[p ^ 1] + ((ks - 2) * 256 + aw * 32) * BATCH);
            const ull* asrc = (const ull*)sA + bp;
            const ull* war  = wAd + (aw * 32) * 16;
#pragma unroll
            for (int kk = 0; kk < 32; ++kk) {
                ull hv = __ldcg(asrc + kk * 32);
                const ulonglong2* wp = (const ulonglong2*)(war + kk * 16);
#pragma unroll
                for (int cp = 0; cp < 8; ++cp) {
                    ulonglong2 w2 = wp[cp];
                    acc[2 * cp]     = fma2(hv, w2.x, acc[2 * cp]);
                    acc[2 * cp + 1] = fma2(hv, w2.y, acc[2 * cp + 1]);
                }
            }
#pragma unroll
            for (int c = 0; c < 16; ++c) redA[(aw * 16 + c) * 32 + bp] = acc[c];
        }
        __syncthreads();

        // ---- reduce both matrices (8-way) + DSMEM scatter, one pass ----
        {
            const int half = tid >> 8;          // 0: h, 1: a
            const int t8   = tid & 255;
            const int c1   = t8 >> 5;           // 0..7
            const int bpR  = t8 & 31;
            ull*     red   = half ? redA : redH;
            unsigned mb_u  = half ? mboxA_u : mboxH_u;
#pragma unroll
            for (int i = 0; i < 2; ++i) {
                const int cc = c1 + i * 8;
                ull s = red[cc * 32 + bpR];
#pragma unroll
                for (int ww = 1; ww < 8; ++ww)
                    s = add2(s, red[(ww * 16 + cc) * 32 + bpR]);
                dsmem_st64(mb_u + (((ks * 4 + (cc & 3)) * 32 + bpR) << 3), cc >> 2, s);
            }
        }
        fence_cluster();
        __syncthreads();
        if (tid < 4) dsmem_st32(mbf_u + ks * 4, tid, r + 2);

        // wait all 4 ranks' slices (equality safe: rounds ordered by leader barrier)
        if (tid < 4) { while (mbf[tid] != r + 2) { } }
        fence_cluster();
        __syncthreads();

        // ---- combine: sum 4 k-split partials, activate, publish ----
        if (tid < 256) {
            if (phC == 0) {
                if (r < S_LEN) {
                    ull v =      mboxH[(0 * 4 + jC) * 32 + bpC];
                    v = add2(v,  mboxH[(1 * 4 + jC) * 32 + bpC]);
                    v = add2(v,  mboxH[(2 * 4 + jC) * 32 + bpC]);
                    v = add2(v,  mboxH[(3 * 4 + jC) * 32 + bpC]);
                    v = add2(v, xwv);
                    float2 f = unpk(v);
                    f.x = tanhf(f.x); f.y = tanhf(f.y);
                    *(ull*)(g_h[p ^ 1] + cC * BATCH + 2 * bpC) = pack2f(f.x, f.y);
                }
            } else {
                float2 f;
                if (r == 0) {
                    f.x = 0.f; f.y = 0.f;                    // a_0 = 0
                } else {
                    ull v =      mboxA[(0 * 4 + jC) * 32 + bpC];
                    v = add2(v,  mboxA[(1 * 4 + jC) * 32 + bpC]);
                    v = add2(v,  mboxA[(2 * 4 + jC) * 32 + bpC]);
                    v = add2(v,  mboxA[(3 * 4 + jC) * 32 + bpC]);
                    f = unpk(v);
                    f.x = tanhf(f.x + biasC); f.y = tanhf(f.y + biasC);
                }
                *(ull*)(g_a[p] + cC * BATCH + 2 * bpC) = pack2f(f.x, f.y);
                if (r == S_LEN) {
                    out[(size_t)(2 * bpC) * EDIM + cC]     = f.x;
                    out[(size_t)(2 * bpC + 1) * EDIM + cC] = f.y;
                }
            }
        }

        // prefetch xw for next round so its latency hides inside the barrier
        if (tid < 128 && r + 1 < S_LEN)
            xwv = __ldcg((const ull*)(g_xw + ((size_t)(r + 1) * HDIM + cC) * BATCH) + bpC);

        if (r < S_LEN) worker_barrier(bid, r + 2);
    }

    // clean exit: no CTA leaves while cluster peers may still scatter to it
    __syncthreads();
    asm volatile("barrier.cluster.arrive.aligned;" ::: "memory");
    asm volatile("barrier.cluster.wait.aligned;" ::: "memory");
}

// ---------------------------------------------------------------------------
extern "C" void kernel_launch(void* const* d_in, const int* in_sizes, int n_in,
                              void* d_out, int out_size) {
    const float* x    = (const float*)d_in[0];
    const float* W_ih = (const float*)d_in[1];
    const float* W_hh = (const float*)d_in[2];
    const float* b_ih = (const float*)d_in[3];
    const float* b_hh = (const float*)d_in[4];
    const float* W_ya = (const float*)d_in[5];
    const float* b_ya = (const float*)d_in[6];
    const float* W_aa = (const float*)d_in[7];
    const float* b_aa = (const float*)d_in[8];
    float* out = (float*)d_out;

    cudaFuncSetAttribute(rnn_all,
                         cudaFuncAttributeMaxDynamicSharedMemorySize, SMEM_BYTES);

    xw_gemm<<<dim3((BATCH * S_LEN) / 64, HDIM / 64), 256>>>(x, W_ih, b_ih, b_hh);
    rnn_all<<<G, NT, SMEM_BYTES>>>(W_hh, W_ya, b_ya, W_aa, b_aa, out);
}